// round 15
// baseline (speedup 1.0000x reference)
#include <cuda_runtime.h>
#include <cuda_fp16.h>
#include <cstdint>

#define BATCH 8
#define DIM   256
#define LQ    1024
#define NH    8
#define HCH   512
#define GK    DIM

// Scratch (allocation-free rule: __device__ globals)
__device__ __align__(256) __half g_qkvh[BATCH * HCH * LQ];  // fp16 qkv (q pre-scaled by 0.25*log2e)
__device__ __align__(256) __half g_xh[BATCH * DIM * LQ];
__device__ __align__(256) __half g_yh[BATCH * DIM * LQ];
__device__ __align__(256) __half g_wqh[HCH * DIM];
__device__ __align__(256) __half g_wph[DIM * DIM];

// ---------------- helpers ----------------------------------------------------
__device__ __forceinline__ void mma16816h(float* d,
    uint32_t a0, uint32_t a1, uint32_t a2, uint32_t a3,
    uint32_t b0, uint32_t b1)
{
    asm volatile(
        "mma.sync.aligned.m16n8k16.row.col.f32.f16.f16.f32 "
        "{%0, %1, %2, %3}, {%4, %5, %6, %7}, {%8, %9}, {%0, %1, %2, %3};"
        : "+f"(d[0]), "+f"(d[1]), "+f"(d[2]), "+f"(d[3])
        : "r"(a0), "r"(a1), "r"(a2), "r"(a3), "r"(b0), "r"(b1));
}
__device__ __forceinline__ uint32_t cvt_h2(float lo, float hi) {
    uint32_t r;
    asm("cvt.rn.f16x2.f32 %0, %1, %2;" : "=r"(r) : "f"(hi), "f"(lo));
    return r;
}
__device__ __forceinline__ uint32_t ex2h2(uint32_t a) {
    uint32_t r;
    asm("ex2.approx.f16x2 %0, %1;" : "=r"(r) : "r"(a));
    return r;
}
__device__ __forceinline__ uint32_t smem_u32(const void* p) {
    uint32_t a;
    asm("{ .reg .u64 t; cvta.to.shared.u64 t, %1; cvt.u32.u64 %0, t; }" : "=r"(a) : "l"(p));
    return a;
}
template<int SH>
__device__ __forceinline__ uint32_t swz(uint32_t off) {
    return off ^ ((off >> SH) & 0x70);
}
__device__ __forceinline__ void cpa16(uint32_t s, const void* g) {
    asm volatile("cp.async.cg.shared.global [%0], [%1], 16;" :: "r"(s), "l"(g) : "memory");
}
__device__ __forceinline__ void ldsm_x4(uint32_t* r, uint32_t a) {
    asm volatile("ldmatrix.sync.aligned.m8n8.x4.shared.b16 {%0,%1,%2,%3}, [%4];"
        : "=r"(r[0]), "=r"(r[1]), "=r"(r[2]), "=r"(r[3]) : "r"(a));
}
__device__ __forceinline__ void ldsm_x4_t(uint32_t* r, uint32_t a) {
    asm volatile("ldmatrix.sync.aligned.m8n8.x4.trans.shared.b16 {%0,%1,%2,%3}, [%4];"
        : "=r"(r[0]), "=r"(r[1]), "=r"(r[2]), "=r"(r[3]) : "r"(a));
}

// ---------------------------------------------------------------------------
// fused convert: x (524288 f4) | w_qkv (32768 f4) | w_proj (16384 f4) -> fp16
// ---------------------------------------------------------------------------
__global__ void __launch_bounds__(256) cvt_all_kernel(
    const float* __restrict__ x, const float* __restrict__ wq,
    const float* __restrict__ wp, __half* __restrict__ xh,
    __half* __restrict__ wqh, __half* __restrict__ wph)
{
    int i = blockIdx.x * 256 + threadIdx.x;
    const float* in; __half* o; int j;
    if (i < 524288)      { in = x;  o = xh;  j = i; }
    else if (i < 557056) { in = wq; o = wqh; j = i - 524288; }
    else                 { in = wp; o = wph; j = i - 557056; }
    float4 v = ((const float4*)in)[j];
    uint2 r;
    r.x = cvt_h2(v.x, v.y);
    r.y = cvt_h2(v.z, v.w);
    ((uint2*)o)[j] = r;
}

// ---------------------------------------------------------------------------
// GEMM v9 (as R14): pair-chunk schedule, __launch_bounds__(256, 2).
// BN=128 tile used for BOTH qkv and proj now (12.3 us/GMAC vs 18.4 for BN=64).
// mode 1 (qkv): fp16 out only, q rows scaled by 0.25*log2e. mode 0: fp32 out.
// ---------------------------------------------------------------------------
template<int BN>
__global__ void __launch_bounds__(256, 2) gemm_v9_kernel(
    const __half* __restrict__ Wh, const __half* __restrict__ Xh,
    const float* __restrict__ bias, float* __restrict__ C,
    __half* __restrict__ Ch, int M, int mode)
{
    extern __shared__ __align__(1024) char smem[];
    constexpr int BSH = (BN == 64) ? 3 : 4;
    constexpr int RB  = BN * 2;
    constexpr int STG = 8192 + 32 * RB;
    constexpr int WN  = BN / 2;
    constexpr int NA  = WN / 8;
    constexpr int NB  = WN / 16;

    const int tid = threadIdx.x, wid = tid >> 5, lane = tid & 31;
    const int g = lane >> 2, tg = lane & 3;
    const int wm = (wid & 3) * 32, wn = (wid >> 2) * WN;
    const int b = blockIdx.z, n0 = blockIdx.x * BN, m0 = blockIdx.y * 128;

    const __half* Xb = Xh + (size_t)b * GK * LQ;
    const uint32_t sb = smem_u32(smem);

    const int am = tid >> 1, ag = (tid & 1) * 2;
    const uint32_t aoff0 = swz<3>(am * 64 + ag * 16);
    const uint32_t aoff1 = swz<3>(am * 64 + (ag + 1) * 16);
    const __half* wa = Wh + (size_t)(m0 + am) * GK + ag * 8;

    float acc[2][NA][4];
    #pragma unroll
    for (int i = 0; i < 2; ++i)
        #pragma unroll
        for (int j = 0; j < NA; ++j)
            #pragma unroll
            for (int r = 0; r < 4; ++r) acc[i][j][r] = 0.f;

    auto stage_ss = [&](int ss) {
        const uint32_t s = sb + (uint32_t)(ss % 6) * STG;
        const int k0 = ss * 32;
        cpa16(s + aoff0, wa + k0);
        cpa16(s + aoff1, wa + k0 + 8);
        #pragma unroll
        for (int r = 0; r < BN / 64; ++r) {
            int idx = tid + r * 256;
            int krow = idx / (BN / 8), bg = idx % (BN / 8);
            cpa16(s + 8192 + swz<BSH>(krow * RB + bg * 16),
                  Xb + (size_t)(k0 + krow) * LQ + n0 + bg * 8);
        }
    };

    auto compute_ss = [&](int ss) {
        const uint32_t s = sb + (uint32_t)(ss % 6) * STG;
        #pragma unroll
        for (int kk = 0; kk < 2; ++kk) {
            uint32_t ah[2][4];
            #pragma unroll
            for (int ma = 0; ma < 2; ++ma)
                ldsm_x4(ah[ma], s + swz<3>((wm + ma * 16 + (lane & 15)) * 64
                                           + kk * 32 + (lane >> 4) * 16));
            uint32_t bh[NB][4];
            #pragma unroll
            for (int nb = 0; nb < NB; ++nb) {
                int krow = kk * 16 + (lane & 7) + ((lane >> 3) & 1) * 8;
                int ncol = wn + nb * 16 + ((lane >> 4) & 1) * 8;
                ldsm_x4_t(bh[nb], s + 8192 + swz<BSH>(krow * RB + ncol * 2));
            }
            #pragma unroll
            for (int ma = 0; ma < 2; ++ma)
                #pragma unroll
                for (int na = 0; na < NA; ++na) {
                    const int nb = na >> 1, o = (na & 1) * 2;
                    mma16816h(acc[ma][na], ah[ma][0], ah[ma][1], ah[ma][2], ah[ma][3],
                              bh[nb][o], bh[nb][o + 1]);
                }
        }
    };

    stage_ss(0); stage_ss(1);
    asm volatile("cp.async.commit_group;" ::: "memory");
    stage_ss(2); stage_ss(3);
    asm volatile("cp.async.commit_group;" ::: "memory");

    #pragma unroll 1
    for (int c = 0; c < 4; ++c) {
        if (c < 3) asm volatile("cp.async.wait_group 1;" ::: "memory");
        else       asm volatile("cp.async.wait_group 0;" ::: "memory");
        __syncthreads();
        compute_ss(2 * c);
        compute_ss(2 * c + 1);
        if (c < 2) {
            stage_ss(2 * c + 4); stage_ss(2 * c + 5);
            asm volatile("cp.async.commit_group;" ::: "memory");
        }
    }

    const float QSC = 0.25f * 1.4426950408889634f;
    float* Cb = C + (size_t)b * M * LQ;
    __half* Chb = Ch + (size_t)b * M * LQ;
    #pragma unroll
    for (int ma = 0; ma < 2; ++ma) {
        const int mrow0 = m0 + wm + ma * 16 + g;
        const float bv0 = bias[mrow0];
        const float bv1 = bias[mrow0 + 8];
        const int cls = ((wm + ma * 16) & 63) >> 4;
        const float qs = (mode == 1 && cls == 0) ? QSC : 1.f;
        #pragma unroll
        for (int na = 0; na < NA; ++na) {
            const int n = n0 + wn + na * 8 + tg * 2;
            float o00 = acc[ma][na][0] + bv0, o01 = acc[ma][na][1] + bv0;
            float o10 = acc[ma][na][2] + bv1, o11 = acc[ma][na][3] + bv1;
            if (mode == 0) {
                *(float2*)&Cb[(size_t)mrow0 * LQ + n]       = make_float2(o00, o01);
                *(float2*)&Cb[(size_t)(mrow0 + 8) * LQ + n] = make_float2(o10, o11);
            } else {
                *(uint32_t*)&Chb[(size_t)mrow0 * LQ + n]       = cvt_h2(o00 * qs, o01 * qs);
                *(uint32_t*)&Chb[(size_t)(mrow0 + 8) * LQ + n] = cvt_h2(o10 * qs, o11 * qs);
            }
        }
    }
}

// ---------------------------------------------------------------------------
// fp16 flash attention + fused PE. Attention is AT the HMMA ceiling, so the
// ones-mma row-sum (1 of 7 HMMA) is replaced by HADD2 + cvt + FADD on the
// idle fma pipe; the tg-group shuffle reduction returns in the epilogue.
// grid = 256 CTAs x 256 threads. dynamic smem 49920 B.
// ---------------------------------------------------------------------------
__global__ void __launch_bounds__(256) attn_tc_kernel(
    const __half* __restrict__ qkvh, const float* __restrict__ w_pe,
    const float* __restrict__ b_pe, __half* __restrict__ yh)
{
    extern __shared__ __align__(16) char smem[];
    __half* Qs = (__half*)smem;                 // [16][264]   (8448 B)
    __half* Ks = (__half*)(smem + 8448);        // 6 x [16][72] (13824 B)
    __half* Vs = (__half*)(smem + 22272);       // 6 x [32][72] (27648 B)
    float*  Os = (float*)smem;                  // [32][265] overlay (post-loop)

    const int tid = threadIdx.x, wid = tid >> 5, lane = tid & 31;
    const int g = lane >> 2, tg = lane & 3;
    const int bx = blockIdx.x;
    const int qb = bx & 3, h = (bx >> 2) & 7, b = bx >> 5;
    const int i0 = qb * 256;
    const __half* base = qkvh + (size_t)b * HCH * LQ + (size_t)h * 64 * LQ;

    auto stage_kv = [&](int ss) {
        const int s6 = ss % 6;
        const int j0 = ss * 64;
        if (tid < 128) {
            int c = tid >> 3, gi = tid & 7;
            cpa16(smem_u32(Ks + s6 * 1152 + c * 72 + gi * 8),
                  base + (size_t)(16 + c) * LQ + j0 + gi * 8);
        }
        int c = tid >> 3, gi = tid & 7;
        cpa16(smem_u32(Vs + s6 * 2304 + c * 72 + gi * 8),
              base + (size_t)(32 + c) * LQ + j0 + gi * 8);
    };

    #pragma unroll
    for (int r = 0; r < 2; ++r) {
        int idx = tid + r * 256;
        int c = idx >> 5, gi = idx & 31;
        cpa16(smem_u32(Qs + c * 264 + gi * 8), base + (size_t)c * LQ + i0 + gi * 8);
    }
    stage_kv(0); stage_kv(1);
    asm volatile("cp.async.commit_group;" ::: "memory");
    stage_kv(2); stage_kv(3);
    asm volatile("cp.async.commit_group;" ::: "memory");

    float acc[2][4][4];
    #pragma unroll
    for (int i = 0; i < 2; ++i)
        #pragma unroll
        for (int j = 0; j < 4; ++j)
            #pragma unroll
            for (int r = 0; r < 4; ++r) acc[i][j][r] = 0.f;
    float lacc[2][2] = {{0.f, 0.f}, {0.f, 0.f}};   // per-thread partial row sums
    uint32_t aQ[2][4];

    const int kc_  = (lane & 7) + ((lane >> 3) & 1) * 8;
    const int koct = ((lane >> 4) & 1) * 8;
    const int qc_  = (lane & 7) + ((lane >> 4) & 1) * 8;
    const int qio  = ((lane >> 3) & 1) * 8;
    const int wq   = wid * 32;

    auto compute_kv = [&](int ss) {
        const int s6 = ss % 6;
        #pragma unroll
        for (int kq = 0; kq < 4; ++kq) {
            uint32_t kf[4];
            ldsm_x4_t(kf, smem_u32(Ks + s6 * 1152 + kc_ * 72 + kq * 16 + koct));
            uint32_t vb[4][2];
            #pragma unroll
            for (int nc = 0; nc < 4; ++nc) {
                const __half* vp = Vs + s6 * 2304 + (nc * 8 + g) * 72 + kq * 16 + 2 * tg;
                vb[nc][0] = *(const uint32_t*)vp;
                vb[nc][1] = *(const uint32_t*)(vp + 8);
            }
            #pragma unroll
            for (int ma = 0; ma < 2; ++ma) {
                float s0[4] = {0.f, 0.f, 0.f, 0.f};
                float s1[4] = {0.f, 0.f, 0.f, 0.f};
                mma16816h(s0, aQ[ma][0], aQ[ma][1], aQ[ma][2], aQ[ma][3], kf[0], kf[1]);
                mma16816h(s1, aQ[ma][0], aQ[ma][1], aQ[ma][2], aQ[ma][3], kf[2], kf[3]);
                uint32_t pa0 = ex2h2(cvt_h2(s0[0], s0[1]));
                uint32_t pa1 = ex2h2(cvt_h2(s0[2], s0[3]));
                uint32_t pa2 = ex2h2(cvt_h2(s1[0], s1[1]));
                uint32_t pa3 = ex2h2(cvt_h2(s1[2], s1[3]));
                #pragma unroll
                for (int nc = 0; nc < 4; ++nc)
                    mma16816h(acc[ma][nc], pa0, pa1, pa2, pa3, vb[nc][0], vb[nc][1]);
                // row sums on the fma pipe (tensor pipe is the binder)
                __half2 h0 = __hadd2(*(__half2*)&pa0, *(__half2*)&pa2);  // row il0
                __half2 h1 = __hadd2(*(__half2*)&pa1, *(__half2*)&pa3);  // row il0+8
                float2 f0 = __half22float2(h0);
                float2 f1 = __half22float2(h1);
                lacc[ma][0] += f0.x + f0.y;
                lacc[ma][1] += f1.x + f1.y;
            }
        }
    };

    #pragma unroll 1
    for (int c = 0; c < 8; ++c) {
        if (c < 7) asm volatile("cp.async.wait_group 1;" ::: "memory");
        else       asm volatile("cp.async.wait_group 0;" ::: "memory");
        __syncthreads();
        if (c == 0) {
            #pragma unroll
            for (int ma = 0; ma < 2; ++ma)
                ldsm_x4_t(aQ[ma], smem_u32(Qs + qc_ * 264 + wq + ma * 16 + qio));
        }
        compute_kv(2 * c);
        compute_kv(2 * c + 1);
        if (c < 6) {
            stage_kv(2 * c + 4); stage_kv(2 * c + 5);
            asm volatile("cp.async.commit_group;" ::: "memory");
        }
    }
    __syncthreads();

    // reduce row sums over the tg group (lane bits 0-1)
    #pragma unroll
    for (int ma = 0; ma < 2; ++ma)
        #pragma unroll
        for (int r = 0; r < 2; ++r) {
            lacc[ma][r] += __shfl_xor_sync(0xffffffffu, lacc[ma][r], 1);
            lacc[ma][r] += __shfl_xor_sync(0xffffffffu, lacc[ma][r], 2);
        }

    #pragma unroll
    for (int ma = 0; ma < 2; ++ma) {
        int il0 = wq + ma * 16 + g;
        float inv0 = 1.f / lacc[ma][0];
        float inv1 = 1.f / lacc[ma][1];
        #pragma unroll
        for (int nc = 0; nc < 4; ++nc) {
            int c = nc * 8 + 2 * tg;
            Os[c * 265 + il0]           = acc[ma][nc][0] * inv0;
            Os[(c + 1) * 265 + il0]     = acc[ma][nc][1] * inv0;
            Os[c * 265 + il0 + 8]       = acc[ma][nc][2] * inv1;
            Os[(c + 1) * 265 + il0 + 8] = acc[ma][nc][3] * inv1;
        }
    }
    __syncthreads();

    {
        const int c  = tid & 31;
        const int ib = (tid >> 5) * 32;
        const int d  = h * 32 + c;
        const __half* vrow = base + (size_t)(32 + c) * LQ;
        __half vwin[48];
        const uint4* src = (const uint4*)(vrow + i0 + ib - 8);
        #pragma unroll
        for (int u = 0; u < 6; ++u) *(uint4*)&vwin[u * 8] = src[u];

        const float w0 = w_pe[d * 3 + 0], w1 = w_pe[d * 3 + 1], w2 = w_pe[d * 3 + 2];
        const float bp = b_pe[d];
        __half* dst = yh + ((size_t)b * DIM + d) * LQ + i0 + ib;
        const float* orow = Os + c * 265 + ib;
        #pragma unroll
        for (int u = 0; u < 32; u += 2) {
            const int l0 = i0 + ib + u;
            float vm = __half2float(vwin[7 + u]);
            float v0 = __half2float(vwin[8 + u]);
            float vp = __half2float(vwin[9 + u]);
            float vq = __half2float(vwin[10 + u]);
            float a0 = bp + orow[u] + w1 * v0 + w2 * vp;
            if (l0 > 0) a0 += w0 * vm;
            float a1 = bp + orow[u + 1] + w0 * v0 + w1 * vp;
            if (l0 < 1022) a1 += w2 * vq;
            *(uint32_t*)&dst[u] = cvt_h2(a0, a1);
        }
    }
}

// ---------------------------------------------------------------------------
extern "C" void kernel_launch(void* const* d_in, const int* in_sizes, int n_in,
                              void* d_out, int out_size)
{
    (void)in_sizes; (void)n_in; (void)out_size;
    const float* x      = (const float*)d_in[0];
    const float* w_qkv  = (const float*)d_in[1];
    const float* b_qkv  = (const float*)d_in[2];
    const float* w_pe   = (const float*)d_in[3];
    const float* b_pe   = (const float*)d_in[4];
    const float* w_proj = (const float*)d_in[5];
    const float* b_proj = (const float*)d_in[6];
    float* out = (float*)d_out;

    __half *qkvh, *xh, *yh, *wqh, *wph;
    cudaGetSymbolAddress((void**)&qkvh, g_qkvh);
    cudaGetSymbolAddress((void**)&xh, g_xh);
    cudaGetSymbolAddress((void**)&yh, g_yh);
    cudaGetSymbolAddress((void**)&wqh, g_wqh);
    cudaGetSymbolAddress((void**)&wph, g_wph);

    cudaFuncSetAttribute(gemm_v9_kernel<128>,
                         cudaFuncAttributeMaxDynamicSharedMemorySize, 98304);
    cudaFuncSetAttribute(attn_tc_kernel,
                         cudaFuncAttributeMaxDynamicSharedMemorySize, 49920);

    // 0) fused fp32->fp16 converts (x, w_qkv, w_proj)
    cvt_all_kernel<<<2240, 256>>>(x, w_qkv, w_proj, xh, wqh, wph);
    // 1) qkv GEMM -> fp16 (q rows pre-scaled by 0.25*log2e), 128x128 tiles
    gemm_v9_kernel<128><<<dim3(LQ / 128, HCH / 128, BATCH), 256, 98304>>>(
        wqh, xh, b_qkv, out, qkvh, HCH, 1);
    // 2) flash attention + fused PE -> fp16 yh (ones-mma removed)
    attn_tc_kernel<<<BATCH * NH * (LQ / 256), 256, 49920>>>(qkvh, w_pe, b_pe, yh);
    // 3) proj GEMM -> fp32 out, 128x128 tiles (grid = 128 CTAs ~ one wave)
    gemm_v9_kernel<128><<<dim3(LQ / 128, DIM / 128, BATCH), 256, 98304>>>(
        wph, yh, b_proj, out, qkvh, DIM, 0);
}

// round 16
// speedup vs baseline: 1.0137x; 1.0137x over previous
#include <cuda_runtime.h>
#include <cuda_fp16.h>
#include <cstdint>

#define BATCH 8
#define DIM   256
#define LQ    1024
#define NH    8
#define HCH   512
#define GK    DIM

// Scratch (allocation-free rule: __device__ globals)
__device__ __align__(256) __half g_qkvh[BATCH * HCH * LQ];  // fp16 qkv (q pre-scaled by 0.25*log2e)
__device__ __align__(256) __half g_xh[BATCH * DIM * LQ];
__device__ __align__(256) __half g_yh[BATCH * DIM * LQ];
__device__ __align__(256) __half g_wqh[HCH * DIM];
__device__ __align__(256) __half g_wph[DIM * DIM];

// ---------------- helpers ----------------------------------------------------
__device__ __forceinline__ void mma16816h(float* d,
    uint32_t a0, uint32_t a1, uint32_t a2, uint32_t a3,
    uint32_t b0, uint32_t b1)
{
    asm volatile(
        "mma.sync.aligned.m16n8k16.row.col.f32.f16.f16.f32 "
        "{%0, %1, %2, %3}, {%4, %5, %6, %7}, {%8, %9}, {%0, %1, %2, %3};"
        : "+f"(d[0]), "+f"(d[1]), "+f"(d[2]), "+f"(d[3])
        : "r"(a0), "r"(a1), "r"(a2), "r"(a3), "r"(b0), "r"(b1));
}
__device__ __forceinline__ uint32_t cvt_h2(float lo, float hi) {
    uint32_t r;
    asm("cvt.rn.f16x2.f32 %0, %1, %2;" : "=r"(r) : "f"(hi), "f"(lo));
    return r;
}
__device__ __forceinline__ uint32_t ex2h2(uint32_t a) {
    uint32_t r;
    asm("ex2.approx.f16x2 %0, %1;" : "=r"(r) : "r"(a));
    return r;
}
__device__ __forceinline__ uint32_t smem_u32(const void* p) {
    uint32_t a;
    asm("{ .reg .u64 t; cvta.to.shared.u64 t, %1; cvt.u32.u64 %0, t; }" : "=r"(a) : "l"(p));
    return a;
}
template<int SH>
__device__ __forceinline__ uint32_t swz(uint32_t off) {
    return off ^ ((off >> SH) & 0x70);
}
__device__ __forceinline__ void cpa16(uint32_t s, const void* g) {
    asm volatile("cp.async.cg.shared.global [%0], [%1], 16;" :: "r"(s), "l"(g) : "memory");
}
__device__ __forceinline__ void ldsm_x4(uint32_t* r, uint32_t a) {
    asm volatile("ldmatrix.sync.aligned.m8n8.x4.shared.b16 {%0,%1,%2,%3}, [%4];"
        : "=r"(r[0]), "=r"(r[1]), "=r"(r[2]), "=r"(r[3]) : "r"(a));
}
__device__ __forceinline__ void ldsm_x4_t(uint32_t* r, uint32_t a) {
    asm volatile("ldmatrix.sync.aligned.m8n8.x4.trans.shared.b16 {%0,%1,%2,%3}, [%4];"
        : "=r"(r[0]), "=r"(r[1]), "=r"(r[2]), "=r"(r[3]) : "r"(a));
}

// ---------------------------------------------------------------------------
// fused convert: x (524288 f4) | w_qkv (32768 f4) | w_proj (16384 f4) -> fp16
// ---------------------------------------------------------------------------
__global__ void __launch_bounds__(256) cvt_all_kernel(
    const float* __restrict__ x, const float* __restrict__ wq,
    const float* __restrict__ wp, __half* __restrict__ xh,
    __half* __restrict__ wqh, __half* __restrict__ wph)
{
    int i = blockIdx.x * 256 + threadIdx.x;
    const float* in; __half* o; int j;
    if (i < 524288)      { in = x;  o = xh;  j = i; }
    else if (i < 557056) { in = wq; o = wqh; j = i - 524288; }
    else                 { in = wp; o = wph; j = i - 557056; }
    float4 v = ((const float4*)in)[j];
    uint2 r;
    r.x = cvt_h2(v.x, v.y);
    r.y = cvt_h2(v.z, v.w);
    ((uint2*)o)[j] = r;
}

// ---------------------------------------------------------------------------
// GEMM v9 (R15 config): pair-chunk schedule, __launch_bounds__(256, 2),
// BN=128 tile for BOTH qkv and proj (best measured us/GMAC).
// mode 1 (qkv): fp16 out only, q rows scaled by 0.25*log2e. mode 0: fp32 out.
// ---------------------------------------------------------------------------
template<int BN>
__global__ void __launch_bounds__(256, 2) gemm_v9_kernel(
    const __half* __restrict__ Wh, const __half* __restrict__ Xh,
    const float* __restrict__ bias, float* __restrict__ C,
    __half* __restrict__ Ch, int M, int mode)
{
    extern __shared__ __align__(1024) char smem[];
    constexpr int BSH = (BN == 64) ? 3 : 4;
    constexpr int RB  = BN * 2;
    constexpr int STG = 8192 + 32 * RB;
    constexpr int WN  = BN / 2;
    constexpr int NA  = WN / 8;
    constexpr int NB  = WN / 16;

    const int tid = threadIdx.x, wid = tid >> 5, lane = tid & 31;
    const int g = lane >> 2, tg = lane & 3;
    const int wm = (wid & 3) * 32, wn = (wid >> 2) * WN;
    const int b = blockIdx.z, n0 = blockIdx.x * BN, m0 = blockIdx.y * 128;

    const __half* Xb = Xh + (size_t)b * GK * LQ;
    const uint32_t sb = smem_u32(smem);

    const int am = tid >> 1, ag = (tid & 1) * 2;
    const uint32_t aoff0 = swz<3>(am * 64 + ag * 16);
    const uint32_t aoff1 = swz<3>(am * 64 + (ag + 1) * 16);
    const __half* wa = Wh + (size_t)(m0 + am) * GK + ag * 8;

    float acc[2][NA][4];
    #pragma unroll
    for (int i = 0; i < 2; ++i)
        #pragma unroll
        for (int j = 0; j < NA; ++j)
            #pragma unroll
            for (int r = 0; r < 4; ++r) acc[i][j][r] = 0.f;

    auto stage_ss = [&](int ss) {
        const uint32_t s = sb + (uint32_t)(ss % 6) * STG;
        const int k0 = ss * 32;
        cpa16(s + aoff0, wa + k0);
        cpa16(s + aoff1, wa + k0 + 8);
        #pragma unroll
        for (int r = 0; r < BN / 64; ++r) {
            int idx = tid + r * 256;
            int krow = idx / (BN / 8), bg = idx % (BN / 8);
            cpa16(s + 8192 + swz<BSH>(krow * RB + bg * 16),
                  Xb + (size_t)(k0 + krow) * LQ + n0 + bg * 8);
        }
    };

    auto compute_ss = [&](int ss) {
        const uint32_t s = sb + (uint32_t)(ss % 6) * STG;
        #pragma unroll
        for (int kk = 0; kk < 2; ++kk) {
            uint32_t ah[2][4];
            #pragma unroll
            for (int ma = 0; ma < 2; ++ma)
                ldsm_x4(ah[ma], s + swz<3>((wm + ma * 16 + (lane & 15)) * 64
                                           + kk * 32 + (lane >> 4) * 16));
            uint32_t bh[NB][4];
            #pragma unroll
            for (int nb = 0; nb < NB; ++nb) {
                int krow = kk * 16 + (lane & 7) + ((lane >> 3) & 1) * 8;
                int ncol = wn + nb * 16 + ((lane >> 4) & 1) * 8;
                ldsm_x4_t(bh[nb], s + 8192 + swz<BSH>(krow * RB + ncol * 2));
            }
            #pragma unroll
            for (int ma = 0; ma < 2; ++ma)
                #pragma unroll
                for (int na = 0; na < NA; ++na) {
                    const int nb = na >> 1, o = (na & 1) * 2;
                    mma16816h(acc[ma][na], ah[ma][0], ah[ma][1], ah[ma][2], ah[ma][3],
                              bh[nb][o], bh[nb][o + 1]);
                }
        }
    };

    stage_ss(0); stage_ss(1);
    asm volatile("cp.async.commit_group;" ::: "memory");
    stage_ss(2); stage_ss(3);
    asm volatile("cp.async.commit_group;" ::: "memory");

    #pragma unroll 1
    for (int c = 0; c < 4; ++c) {
        if (c < 3) asm volatile("cp.async.wait_group 1;" ::: "memory");
        else       asm volatile("cp.async.wait_group 0;" ::: "memory");
        __syncthreads();
        compute_ss(2 * c);
        compute_ss(2 * c + 1);
        if (c < 2) {
            stage_ss(2 * c + 4); stage_ss(2 * c + 5);
            asm volatile("cp.async.commit_group;" ::: "memory");
        }
    }

    const float QSC = 0.25f * 1.4426950408889634f;
    float* Cb = C + (size_t)b * M * LQ;
    __half* Chb = Ch + (size_t)b * M * LQ;
    #pragma unroll
    for (int ma = 0; ma < 2; ++ma) {
        const int mrow0 = m0 + wm + ma * 16 + g;
        const float bv0 = bias[mrow0];
        const float bv1 = bias[mrow0 + 8];
        const int cls = ((wm + ma * 16) & 63) >> 4;
        const float qs = (mode == 1 && cls == 0) ? QSC : 1.f;
        #pragma unroll
        for (int na = 0; na < NA; ++na) {
            const int n = n0 + wn + na * 8 + tg * 2;
            float o00 = acc[ma][na][0] + bv0, o01 = acc[ma][na][1] + bv0;
            float o10 = acc[ma][na][2] + bv1, o11 = acc[ma][na][3] + bv1;
            if (mode == 0) {
                *(float2*)&Cb[(size_t)mrow0 * LQ + n]       = make_float2(o00, o01);
                *(float2*)&Cb[(size_t)(mrow0 + 8) * LQ + n] = make_float2(o10, o11);
            } else {
                *(uint32_t*)&Chb[(size_t)mrow0 * LQ + n]       = cvt_h2(o00 * qs, o01 * qs);
                *(uint32_t*)&Chb[(size_t)(mrow0 + 8) * LQ + n] = cvt_h2(o10 * qs, o11 * qs);
            }
        }
    }
}

// ---------------------------------------------------------------------------
// fp16 flash attention + fused PE. R14 arithmetic (ones-mma row sums) with
// QUAD-chunk schedule: 256 keys per barrier -> 4 syncs total, 3-quad
// (12-substage) K/V ring. SMEM 91392 B -> 2 CTAs/SM (grid is 1.73/SM anyway).
// grid = 256 CTAs x 256 threads.
// ---------------------------------------------------------------------------
#define ATTN_SMEM 91392
__global__ void __launch_bounds__(256) attn_tc_kernel(
    const __half* __restrict__ qkvh, const float* __restrict__ w_pe,
    const float* __restrict__ b_pe, __half* __restrict__ yh)
{
    extern __shared__ __align__(16) char smem[];
    __half* Qs = (__half*)smem;                 // [16][264]     (8448 B)
    __half* Ks = (__half*)(smem + 8448);        // 12 x [16][72] (27648 B)
    __half* Vs = (__half*)(smem + 36096);       // 12 x [32][72] (55296 B)
    float*  Os = (float*)smem;                  // [32][265] overlay (post-loop)

    const int tid = threadIdx.x, wid = tid >> 5, lane = tid & 31;
    const int g = lane >> 2, tg = lane & 3;
    const int bx = blockIdx.x;
    const int qb = bx & 3, h = (bx >> 2) & 7, b = bx >> 5;
    const int i0 = qb * 256;
    const __half* base = qkvh + (size_t)b * HCH * LQ + (size_t)h * 64 * LQ;
    const uint32_t ONES = 0x3C003C00u;

    auto stage_kv = [&](int ss) {
        const int s12 = ss % 12;
        const int j0 = ss * 64;
        if (tid < 128) {
            int c = tid >> 3, gi = tid & 7;
            cpa16(smem_u32(Ks + s12 * 1152 + c * 72 + gi * 8),
                  base + (size_t)(16 + c) * LQ + j0 + gi * 8);
        }
        int c = tid >> 3, gi = tid & 7;
        cpa16(smem_u32(Vs + s12 * 2304 + c * 72 + gi * 8),
              base + (size_t)(32 + c) * LQ + j0 + gi * 8);
    };
    auto stage_quad = [&](int q) {
        stage_kv(4 * q); stage_kv(4 * q + 1);
        stage_kv(4 * q + 2); stage_kv(4 * q + 3);
        asm volatile("cp.async.commit_group;" ::: "memory");
    };

    #pragma unroll
    for (int r = 0; r < 2; ++r) {
        int idx = tid + r * 256;
        int c = idx >> 5, gi = idx & 31;
        cpa16(smem_u32(Qs + c * 264 + gi * 8), base + (size_t)c * LQ + i0 + gi * 8);
    }
    stage_quad(0);
    stage_quad(1);

    float acc[2][4][4];
    #pragma unroll
    for (int i = 0; i < 2; ++i)
        #pragma unroll
        for (int j = 0; j < 4; ++j)
            #pragma unroll
            for (int r = 0; r < 4; ++r) acc[i][j][r] = 0.f;
    float accl[2][4];
    #pragma unroll
    for (int i = 0; i < 2; ++i)
        #pragma unroll
        for (int r = 0; r < 4; ++r) accl[i][r] = 0.f;
    uint32_t aQ[2][4];

    const int kc_  = (lane & 7) + ((lane >> 3) & 1) * 8;
    const int koct = ((lane >> 4) & 1) * 8;
    const int qc_  = (lane & 7) + ((lane >> 4) & 1) * 8;
    const int qio  = ((lane >> 3) & 1) * 8;
    const int wq   = wid * 32;

    auto compute_kv = [&](int ss) {
        const int s12 = ss % 12;
        #pragma unroll
        for (int kq = 0; kq < 4; ++kq) {
            uint32_t kf[4];
            ldsm_x4_t(kf, smem_u32(Ks + s12 * 1152 + kc_ * 72 + kq * 16 + koct));
            uint32_t vb[4][2];
            #pragma unroll
            for (int nc = 0; nc < 4; ++nc) {
                const __half* vp = Vs + s12 * 2304 + (nc * 8 + g) * 72 + kq * 16 + 2 * tg;
                vb[nc][0] = *(const uint32_t*)vp;
                vb[nc][1] = *(const uint32_t*)(vp + 8);
            }
            #pragma unroll
            for (int ma = 0; ma < 2; ++ma) {
                float s0[4] = {0.f, 0.f, 0.f, 0.f};
                float s1[4] = {0.f, 0.f, 0.f, 0.f};
                mma16816h(s0, aQ[ma][0], aQ[ma][1], aQ[ma][2], aQ[ma][3], kf[0], kf[1]);
                mma16816h(s1, aQ[ma][0], aQ[ma][1], aQ[ma][2], aQ[ma][3], kf[2], kf[3]);
                uint32_t pa0 = ex2h2(cvt_h2(s0[0], s0[1]));
                uint32_t pa1 = ex2h2(cvt_h2(s0[2], s0[3]));
                uint32_t pa2 = ex2h2(cvt_h2(s1[0], s1[1]));
                uint32_t pa3 = ex2h2(cvt_h2(s1[2], s1[3]));
                #pragma unroll
                for (int nc = 0; nc < 4; ++nc)
                    mma16816h(acc[ma][nc], pa0, pa1, pa2, pa3, vb[nc][0], vb[nc][1]);
                mma16816h(accl[ma], pa0, pa1, pa2, pa3, ONES, ONES);
            }
        }
    };

    #pragma unroll 1
    for (int c = 0; c < 4; ++c) {
        if (c < 3) asm volatile("cp.async.wait_group 1;" ::: "memory");
        else       asm volatile("cp.async.wait_group 0;" ::: "memory");
        __syncthreads();
        if (c == 0) {
            #pragma unroll
            for (int ma = 0; ma < 2; ++ma)
                ldsm_x4_t(aQ[ma], smem_u32(Qs + qc_ * 264 + wq + ma * 16 + qio));
        }
        compute_kv(4 * c);
        compute_kv(4 * c + 1);
        compute_kv(4 * c + 2);
        compute_kv(4 * c + 3);
        if (c < 2) stage_quad(c + 2);
    }
    __syncthreads();   // all compute done before Os overlays staging buffers

    #pragma unroll
    for (int ma = 0; ma < 2; ++ma) {
        int il0 = wq + ma * 16 + g;
        float inv0 = 1.f / accl[ma][0];
        float inv1 = 1.f / accl[ma][2];
        #pragma unroll
        for (int nc = 0; nc < 4; ++nc) {
            int c = nc * 8 + 2 * tg;
            Os[c * 265 + il0]           = acc[ma][nc][0] * inv0;
            Os[(c + 1) * 265 + il0]     = acc[ma][nc][1] * inv0;
            Os[c * 265 + il0 + 8]       = acc[ma][nc][2] * inv1;
            Os[(c + 1) * 265 + il0 + 8] = acc[ma][nc][3] * inv1;
        }
    }
    __syncthreads();

    {
        const int c  = tid & 31;
        const int ib = (tid >> 5) * 32;
        const int d  = h * 32 + c;
        const __half* vrow = base + (size_t)(32 + c) * LQ;
        __half vwin[48];
        const uint4* src = (const uint4*)(vrow + i0 + ib - 8);
        #pragma unroll
        for (int u = 0; u < 6; ++u) *(uint4*)&vwin[u * 8] = src[u];

        const float w0 = w_pe[d * 3 + 0], w1 = w_pe[d * 3 + 1], w2 = w_pe[d * 3 + 2];
        const float bp = b_pe[d];
        __half* dst = yh + ((size_t)b * DIM + d) * LQ + i0 + ib;
        const float* orow = Os + c * 265 + ib;
        #pragma unroll
        for (int u = 0; u < 32; u += 2) {
            const int l0 = i0 + ib + u;
            float vm = __half2float(vwin[7 + u]);
            float v0 = __half2float(vwin[8 + u]);
            float vp = __half2float(vwin[9 + u]);
            float vq = __half2float(vwin[10 + u]);
            float a0 = bp + orow[u] + w1 * v0 + w2 * vp;
            if (l0 > 0) a0 += w0 * vm;
            float a1 = bp + orow[u + 1] + w0 * v0 + w1 * vp;
            if (l0 < 1022) a1 += w2 * vq;
            *(uint32_t*)&dst[u] = cvt_h2(a0, a1);
        }
    }
}

// ---------------------------------------------------------------------------
extern "C" void kernel_launch(void* const* d_in, const int* in_sizes, int n_in,
                              void* d_out, int out_size)
{
    (void)in_sizes; (void)n_in; (void)out_size;
    const float* x      = (const float*)d_in[0];
    const float* w_qkv  = (const float*)d_in[1];
    const float* b_qkv  = (const float*)d_in[2];
    const float* w_pe   = (const float*)d_in[3];
    const float* b_pe   = (const float*)d_in[4];
    const float* w_proj = (const float*)d_in[5];
    const float* b_proj = (const float*)d_in[6];
    float* out = (float*)d_out;

    __half *qkvh, *xh, *yh, *wqh, *wph;
    cudaGetSymbolAddress((void**)&qkvh, g_qkvh);
    cudaGetSymbolAddress((void**)&xh, g_xh);
    cudaGetSymbolAddress((void**)&yh, g_yh);
    cudaGetSymbolAddress((void**)&wqh, g_wqh);
    cudaGetSymbolAddress((void**)&wph, g_wph);

    cudaFuncSetAttribute(gemm_v9_kernel<128>,
                         cudaFuncAttributeMaxDynamicSharedMemorySize, 98304);
    cudaFuncSetAttribute(attn_tc_kernel,
                         cudaFuncAttributeMaxDynamicSharedMemorySize, ATTN_SMEM);

    // 0) fused fp32->fp16 converts (x, w_qkv, w_proj)
    cvt_all_kernel<<<2240, 256>>>(x, w_qkv, w_proj, xh, wqh, wph);
    // 1) qkv GEMM -> fp16 (q rows pre-scaled by 0.25*log2e), 128x128 tiles
    gemm_v9_kernel<128><<<dim3(LQ / 128, HCH / 128, BATCH), 256, 98304>>>(
        wqh, xh, b_qkv, out, qkvh, HCH, 1);
    // 2) flash attention + fused PE -> fp16 yh (quad-chunk, 4 barriers)
    attn_tc_kernel<<<BATCH * NH * (LQ / 256), 256, ATTN_SMEM>>>(qkvh, w_pe, b_pe, yh);
    // 3) proj GEMM -> fp32 out, 128x128 tiles (grid = 128 CTAs, single wave)
    gemm_v9_kernel<128><<<dim3(LQ / 128, DIM / 128, BATCH), 256, 98304>>>(
        wph, yh, b_proj, out, qkvh, DIM, 0);
}

// round 17
// speedup vs baseline: 1.0471x; 1.0329x over previous
#include <cuda_runtime.h>
#include <cuda_fp16.h>
#include <cstdint>

#define BATCH 8
#define DIM   256
#define LQ    1024
#define NH    8
#define HCH   512
#define GK    DIM

// Scratch (allocation-free rule: __device__ globals)
__device__ __align__(256) __half g_qkvh[BATCH * HCH * LQ];  // fp16 qkv (q pre-scaled by 0.25*log2e)
__device__ __align__(256) __half g_xh[BATCH * DIM * LQ];
__device__ __align__(256) __half g_yh[BATCH * DIM * LQ];
__device__ __align__(256) __half g_wqh[HCH * DIM];
__device__ __align__(256) __half g_wph[DIM * DIM];

// ---------------- helpers ----------------------------------------------------
__device__ __forceinline__ void mma16816h(float* d,
    uint32_t a0, uint32_t a1, uint32_t a2, uint32_t a3,
    uint32_t b0, uint32_t b1)
{
    asm volatile(
        "mma.sync.aligned.m16n8k16.row.col.f32.f16.f16.f32 "
        "{%0, %1, %2, %3}, {%4, %5, %6, %7}, {%8, %9}, {%0, %1, %2, %3};"
        : "+f"(d[0]), "+f"(d[1]), "+f"(d[2]), "+f"(d[3])
        : "r"(a0), "r"(a1), "r"(a2), "r"(a3), "r"(b0), "r"(b1));
}
__device__ __forceinline__ uint32_t cvt_h2(float lo, float hi) {
    uint32_t r;
    asm("cvt.rn.f16x2.f32 %0, %1, %2;" : "=r"(r) : "f"(hi), "f"(lo));
    return r;
}
__device__ __forceinline__ uint32_t ex2h2(uint32_t a) {
    uint32_t r;
    asm("ex2.approx.f16x2 %0, %1;" : "=r"(r) : "r"(a));
    return r;
}
__device__ __forceinline__ uint32_t smem_u32(const void* p) {
    uint32_t a;
    asm("{ .reg .u64 t; cvta.to.shared.u64 t, %1; cvt.u32.u64 %0, t; }" : "=r"(a) : "l"(p));
    return a;
}
template<int SH>
__device__ __forceinline__ uint32_t swz(uint32_t off) {
    return off ^ ((off >> SH) & 0x70);
}
__device__ __forceinline__ void cpa16(uint32_t s, const void* g) {
    asm volatile("cp.async.cg.shared.global [%0], [%1], 16;" :: "r"(s), "l"(g) : "memory");
}
__device__ __forceinline__ void ldsm_x4(uint32_t* r, uint32_t a) {
    asm volatile("ldmatrix.sync.aligned.m8n8.x4.shared.b16 {%0,%1,%2,%3}, [%4];"
        : "=r"(r[0]), "=r"(r[1]), "=r"(r[2]), "=r"(r[3]) : "r"(a));
}
__device__ __forceinline__ void ldsm_x4_t(uint32_t* r, uint32_t a) {
    asm volatile("ldmatrix.sync.aligned.m8n8.x4.trans.shared.b16 {%0,%1,%2,%3}, [%4];"
        : "=r"(r[0]), "=r"(r[1]), "=r"(r[2]), "=r"(r[3]) : "r"(a));
}

// ---------------------------------------------------------------------------
// fused convert: x (524288 f4) | w_qkv (32768 f4) | w_proj (16384 f4) -> fp16
// ---------------------------------------------------------------------------
__global__ void __launch_bounds__(256) cvt_all_kernel(
    const float* __restrict__ x, const float* __restrict__ wq,
    const float* __restrict__ wp, __half* __restrict__ xh,
    __half* __restrict__ wqh, __half* __restrict__ wph)
{
    int i = blockIdx.x * 256 + threadIdx.x;
    const float* in; __half* o; int j;
    if (i < 524288)      { in = x;  o = xh;  j = i; }
    else if (i < 557056) { in = wq; o = wqh; j = i - 524288; }
    else                 { in = wp; o = wph; j = i - 557056; }
    float4 v = ((const float4*)in)[j];
    uint2 r;
    r.x = cvt_h2(v.x, v.y);
    r.y = cvt_h2(v.z, v.w);
    ((uint2*)o)[j] = r;
}

// ---------------------------------------------------------------------------
// GEMM v9 (R16 config, unchanged): pair-chunk, __launch_bounds__(256, 2),
// BN=128 tile for both qkv and proj.
// mode 1 (qkv): fp16 out only, q rows scaled by 0.25*log2e. mode 0: fp32 out.
// ---------------------------------------------------------------------------
template<int BN>
__global__ void __launch_bounds__(256, 2) gemm_v9_kernel(
    const __half* __restrict__ Wh, const __half* __restrict__ Xh,
    const float* __restrict__ bias, float* __restrict__ C,
    __half* __restrict__ Ch, int M, int mode)
{
    extern __shared__ __align__(1024) char smem[];
    constexpr int BSH = (BN == 64) ? 3 : 4;
    constexpr int RB  = BN * 2;
    constexpr int STG = 8192 + 32 * RB;
    constexpr int WN  = BN / 2;
    constexpr int NA  = WN / 8;
    constexpr int NB  = WN / 16;

    const int tid = threadIdx.x, wid = tid >> 5, lane = tid & 31;
    const int g = lane >> 2, tg = lane & 3;
    const int wm = (wid & 3) * 32, wn = (wid >> 2) * WN;
    const int b = blockIdx.z, n0 = blockIdx.x * BN, m0 = blockIdx.y * 128;

    const __half* Xb = Xh + (size_t)b * GK * LQ;
    const uint32_t sb = smem_u32(smem);

    const int am = tid >> 1, ag = (tid & 1) * 2;
    const uint32_t aoff0 = swz<3>(am * 64 + ag * 16);
    const uint32_t aoff1 = swz<3>(am * 64 + (ag + 1) * 16);
    const __half* wa = Wh + (size_t)(m0 + am) * GK + ag * 8;

    float acc[2][NA][4];
    #pragma unroll
    for (int i = 0; i < 2; ++i)
        #pragma unroll
        for (int j = 0; j < NA; ++j)
            #pragma unroll
            for (int r = 0; r < 4; ++r) acc[i][j][r] = 0.f;

    auto stage_ss = [&](int ss) {
        const uint32_t s = sb + (uint32_t)(ss % 6) * STG;
        const int k0 = ss * 32;
        cpa16(s + aoff0, wa + k0);
        cpa16(s + aoff1, wa + k0 + 8);
        #pragma unroll
        for (int r = 0; r < BN / 64; ++r) {
            int idx = tid + r * 256;
            int krow = idx / (BN / 8), bg = idx % (BN / 8);
            cpa16(s + 8192 + swz<BSH>(krow * RB + bg * 16),
                  Xb + (size_t)(k0 + krow) * LQ + n0 + bg * 8);
        }
    };

    auto compute_ss = [&](int ss) {
        const uint32_t s = sb + (uint32_t)(ss % 6) * STG;
        #pragma unroll
        for (int kk = 0; kk < 2; ++kk) {
            uint32_t ah[2][4];
            #pragma unroll
            for (int ma = 0; ma < 2; ++ma)
                ldsm_x4(ah[ma], s + swz<3>((wm + ma * 16 + (lane & 15)) * 64
                                           + kk * 32 + (lane >> 4) * 16));
            uint32_t bh[NB][4];
            #pragma unroll
            for (int nb = 0; nb < NB; ++nb) {
                int krow = kk * 16 + (lane & 7) + ((lane >> 3) & 1) * 8;
                int ncol = wn + nb * 16 + ((lane >> 4) & 1) * 8;
                ldsm_x4_t(bh[nb], s + 8192 + swz<BSH>(krow * RB + ncol * 2));
            }
            #pragma unroll
            for (int ma = 0; ma < 2; ++ma)
                #pragma unroll
                for (int na = 0; na < NA; ++na) {
                    const int nb = na >> 1, o = (na & 1) * 2;
                    mma16816h(acc[ma][na], ah[ma][0], ah[ma][1], ah[ma][2], ah[ma][3],
                              bh[nb][o], bh[nb][o + 1]);
                }
        }
    };

    stage_ss(0); stage_ss(1);
    asm volatile("cp.async.commit_group;" ::: "memory");
    stage_ss(2); stage_ss(3);
    asm volatile("cp.async.commit_group;" ::: "memory");

    #pragma unroll 1
    for (int c = 0; c < 4; ++c) {
        if (c < 3) asm volatile("cp.async.wait_group 1;" ::: "memory");
        else       asm volatile("cp.async.wait_group 0;" ::: "memory");
        __syncthreads();
        compute_ss(2 * c);
        compute_ss(2 * c + 1);
        if (c < 2) {
            stage_ss(2 * c + 4); stage_ss(2 * c + 5);
            asm volatile("cp.async.commit_group;" ::: "memory");
        }
    }

    const float QSC = 0.25f * 1.4426950408889634f;
    float* Cb = C + (size_t)b * M * LQ;
    __half* Chb = Ch + (size_t)b * M * LQ;
    #pragma unroll
    for (int ma = 0; ma < 2; ++ma) {
        const int mrow0 = m0 + wm + ma * 16 + g;
        const float bv0 = bias[mrow0];
        const float bv1 = bias[mrow0 + 8];
        const int cls = ((wm + ma * 16) & 63) >> 4;
        const float qs = (mode == 1 && cls == 0) ? QSC : 1.f;
        #pragma unroll
        for (int na = 0; na < NA; ++na) {
            const int n = n0 + wn + na * 8 + tg * 2;
            float o00 = acc[ma][na][0] + bv0, o01 = acc[ma][na][1] + bv0;
            float o10 = acc[ma][na][2] + bv1, o11 = acc[ma][na][3] + bv1;
            if (mode == 0) {
                *(float2*)&Cb[(size_t)mrow0 * LQ + n]       = make_float2(o00, o01);
                *(float2*)&Cb[(size_t)(mrow0 + 8) * LQ + n] = make_float2(o10, o11);
            } else {
                *(uint32_t*)&Chb[(size_t)mrow0 * LQ + n]       = cvt_h2(o00 * qs, o01 * qs);
                *(uint32_t*)&Chb[(size_t)(mrow0 + 8) * LQ + n] = cvt_h2(o10 * qs, o11 * qs);
            }
        }
    }
}

// ---------------------------------------------------------------------------
// fp16 flash attention + fused PE. Quad-chunk (R16). NEW: per-kq the two ma
// sub-tiles are batched -- all 4 S-mma issue first, then all cvt/ex2, then
// all PV/ones-mma -- so the S->cvt->ex2->PV latency chain is exposed once
// per kq instead of twice (asm volatile blocks compiler reordering).
// PE v-window loads hoisted ahead of the epilogue transpose.
// grid = 256 CTAs x 256 threads. dynamic smem 91392 B.
// ---------------------------------------------------------------------------
#define ATTN_SMEM 91392
__global__ void __launch_bounds__(256, 2) attn_tc_kernel(
    const __half* __restrict__ qkvh, const float* __restrict__ w_pe,
    const float* __restrict__ b_pe, __half* __restrict__ yh)
{
    extern __shared__ __align__(16) char smem[];
    __half* Qs = (__half*)smem;                 // [16][264]     (8448 B)
    __half* Ks = (__half*)(smem + 8448);        // 12 x [16][72] (27648 B)
    __half* Vs = (__half*)(smem + 36096);       // 12 x [32][72] (55296 B)
    float*  Os = (float*)smem;                  // [32][265] overlay (post-loop)

    const int tid = threadIdx.x, wid = tid >> 5, lane = tid & 31;
    const int g = lane >> 2, tg = lane & 3;
    const int bx = blockIdx.x;
    const int qb = bx & 3, h = (bx >> 2) & 7, b = bx >> 5;
    const int i0 = qb * 256;
    const __half* base = qkvh + (size_t)b * HCH * LQ + (size_t)h * 64 * LQ;
    const uint32_t ONES = 0x3C003C00u;

    auto stage_kv = [&](int ss) {
        const int s12 = ss % 12;
        const int j0 = ss * 64;
        if (tid < 128) {
            int c = tid >> 3, gi = tid & 7;
            cpa16(smem_u32(Ks + s12 * 1152 + c * 72 + gi * 8),
                  base + (size_t)(16 + c) * LQ + j0 + gi * 8);
        }
        int c = tid >> 3, gi = tid & 7;
        cpa16(smem_u32(Vs + s12 * 2304 + c * 72 + gi * 8),
              base + (size_t)(32 + c) * LQ + j0 + gi * 8);
    };
    auto stage_quad = [&](int q) {
        stage_kv(4 * q); stage_kv(4 * q + 1);
        stage_kv(4 * q + 2); stage_kv(4 * q + 3);
        asm volatile("cp.async.commit_group;" ::: "memory");
    };

    #pragma unroll
    for (int r = 0; r < 2; ++r) {
        int idx = tid + r * 256;
        int c = idx >> 5, gi = idx & 31;
        cpa16(smem_u32(Qs + c * 264 + gi * 8), base + (size_t)c * LQ + i0 + gi * 8);
    }
    stage_quad(0);
    stage_quad(1);

    float acc[2][4][4];
    #pragma unroll
    for (int i = 0; i < 2; ++i)
        #pragma unroll
        for (int j = 0; j < 4; ++j)
            #pragma unroll
            for (int r = 0; r < 4; ++r) acc[i][j][r] = 0.f;
    float accl[2][4];
    #pragma unroll
    for (int i = 0; i < 2; ++i)
        #pragma unroll
        for (int r = 0; r < 4; ++r) accl[i][r] = 0.f;
    uint32_t aQ[2][4];

    const int kc_  = (lane & 7) + ((lane >> 3) & 1) * 8;
    const int koct = ((lane >> 4) & 1) * 8;
    const int qc_  = (lane & 7) + ((lane >> 4) & 1) * 8;
    const int qio  = ((lane >> 3) & 1) * 8;
    const int wq   = wid * 32;

    auto compute_kv = [&](int ss) {
        const int s12 = ss % 12;
        #pragma unroll
        for (int kq = 0; kq < 4; ++kq) {
            uint32_t kf[4];
            ldsm_x4_t(kf, smem_u32(Ks + s12 * 1152 + kc_ * 72 + kq * 16 + koct));
            uint32_t vb[4][2];
            #pragma unroll
            for (int nc = 0; nc < 4; ++nc) {
                const __half* vp = Vs + s12 * 2304 + (nc * 8 + g) * 72 + kq * 16 + 2 * tg;
                vb[nc][0] = *(const uint32_t*)vp;
                vb[nc][1] = *(const uint32_t*)(vp + 8);
            }
            // phase 1: all 4 independent S-mma (both ma)
            float s0[2][4], s1[2][4];
            #pragma unroll
            for (int ma = 0; ma < 2; ++ma) {
                #pragma unroll
                for (int r = 0; r < 4; ++r) { s0[ma][r] = 0.f; s1[ma][r] = 0.f; }
                mma16816h(s0[ma], aQ[ma][0], aQ[ma][1], aQ[ma][2], aQ[ma][3], kf[0], kf[1]);
                mma16816h(s1[ma], aQ[ma][0], aQ[ma][1], aQ[ma][2], aQ[ma][3], kf[2], kf[3]);
            }
            // phase 2: all conversions (non-volatile: scheduler-movable)
            uint32_t pa[2][4];
            #pragma unroll
            for (int ma = 0; ma < 2; ++ma) {
                pa[ma][0] = ex2h2(cvt_h2(s0[ma][0], s0[ma][1]));
                pa[ma][1] = ex2h2(cvt_h2(s0[ma][2], s0[ma][3]));
                pa[ma][2] = ex2h2(cvt_h2(s1[ma][0], s1[ma][1]));
                pa[ma][3] = ex2h2(cvt_h2(s1[ma][2], s1[ma][3]));
            }
            // phase 3: all PV + ones mma
            #pragma unroll
            for (int ma = 0; ma < 2; ++ma) {
                #pragma unroll
                for (int nc = 0; nc < 4; ++nc)
                    mma16816h(acc[ma][nc], pa[ma][0], pa[ma][1], pa[ma][2], pa[ma][3],
                              vb[nc][0], vb[nc][1]);
                mma16816h(accl[ma], pa[ma][0], pa[ma][1], pa[ma][2], pa[ma][3], ONES, ONES);
            }
        }
    };

    #pragma unroll 1
    for (int c = 0; c < 4; ++c) {
        if (c < 3) asm volatile("cp.async.wait_group 1;" ::: "memory");
        else       asm volatile("cp.async.wait_group 0;" ::: "memory");
        __syncthreads();
        if (c == 0) {
            #pragma unroll
            for (int ma = 0; ma < 2; ++ma)
                ldsm_x4_t(aQ[ma], smem_u32(Qs + qc_ * 264 + wq + ma * 16 + qio));
        }
        compute_kv(4 * c);
        compute_kv(4 * c + 1);
        compute_kv(4 * c + 2);
        compute_kv(4 * c + 3);
        if (c < 2) stage_quad(c + 2);
    }
    __syncthreads();   // all compute done before Os overlays staging buffers

    // PE v-window prefetch (global loads overlap the transpose smem writes)
    const int pc  = tid & 31;
    const int pib = (tid >> 5) * 32;
    __half vwin[48];
    {
        const __half* vrow = base + (size_t)(32 + pc) * LQ;
        const uint4* src = (const uint4*)(vrow + i0 + pib - 8);
        #pragma unroll
        for (int u = 0; u < 6; ++u) *(uint4*)&vwin[u * 8] = src[u];
    }

    #pragma unroll
    for (int ma = 0; ma < 2; ++ma) {
        int il0 = wq + ma * 16 + g;
        float inv0 = 1.f / accl[ma][0];
        float inv1 = 1.f / accl[ma][2];
        #pragma unroll
        for (int nc = 0; nc < 4; ++nc) {
            int c = nc * 8 + 2 * tg;
            Os[c * 265 + il0]           = acc[ma][nc][0] * inv0;
            Os[(c + 1) * 265 + il0]     = acc[ma][nc][1] * inv0;
            Os[c * 265 + il0 + 8]       = acc[ma][nc][2] * inv1;
            Os[(c + 1) * 265 + il0 + 8] = acc[ma][nc][3] * inv1;
        }
    }
    __syncthreads();

    {
        const int d = h * 32 + pc;
        const float w0 = w_pe[d * 3 + 0], w1 = w_pe[d * 3 + 1], w2 = w_pe[d * 3 + 2];
        const float bp = b_pe[d];
        __half* dst = yh + ((size_t)b * DIM + d) * LQ + i0 + pib;
        const float* orow = Os + pc * 265 + pib;
        #pragma unroll
        for (int u = 0; u < 32; u += 2) {
            const int l0 = i0 + pib + u;
            float vm = __half2float(vwin[7 + u]);
            float v0 = __half2float(vwin[8 + u]);
            float vp = __half2float(vwin[9 + u]);
            float vq = __half2float(vwin[10 + u]);
            float a0 = bp + orow[u] + w1 * v0 + w2 * vp;
            if (l0 > 0) a0 += w0 * vm;
            float a1 = bp + orow[u + 1] + w0 * v0 + w1 * vp;
            if (l0 < 1022) a1 += w2 * vq;
            *(uint32_t*)&dst[u] = cvt_h2(a0, a1);
        }
    }
}

// ---------------------------------------------------------------------------
extern "C" void kernel_launch(void* const* d_in, const int* in_sizes, int n_in,
                              void* d_out, int out_size)
{
    (void)in_sizes; (void)n_in; (void)out_size;
    const float* x      = (const float*)d_in[0];
    const float* w_qkv  = (const float*)d_in[1];
    const float* b_qkv  = (const float*)d_in[2];
    const float* w_pe   = (const float*)d_in[3];
    const float* b_pe   = (const float*)d_in[4];
    const float* w_proj = (const float*)d_in[5];
    const float* b_proj = (const float*)d_in[6];
    float* out = (float*)d_out;

    __half *qkvh, *xh, *yh, *wqh, *wph;
    cudaGetSymbolAddress((void**)&qkvh, g_qkvh);
    cudaGetSymbolAddress((void**)&xh, g_xh);
    cudaGetSymbolAddress((void**)&yh, g_yh);
    cudaGetSymbolAddress((void**)&wqh, g_wqh);
    cudaGetSymbolAddress((void**)&wph, g_wph);

    cudaFuncSetAttribute(gemm_v9_kernel<128>,
                         cudaFuncAttributeMaxDynamicSharedMemorySize, 98304);
    cudaFuncSetAttribute(attn_tc_kernel,
                         cudaFuncAttributeMaxDynamicSharedMemorySize, ATTN_SMEM);

    // 0) fused fp32->fp16 converts (x, w_qkv, w_proj)
    cvt_all_kernel<<<2240, 256>>>(x, w_qkv, w_proj, xh, wqh, wph);
    // 1) qkv GEMM -> fp16 (q rows pre-scaled by 0.25*log2e), 128x128 tiles
    gemm_v9_kernel<128><<<dim3(LQ / 128, HCH / 128, BATCH), 256, 98304>>>(
        wqh, xh, b_qkv, out, qkvh, HCH, 1);
    // 2) flash attention + fused PE -> fp16 yh (quad-chunk, ma-batched softmax)
    attn_tc_kernel<<<BATCH * NH * (LQ / 256), 256, ATTN_SMEM>>>(qkvh, w_pe, b_pe, yh);
    // 3) proj GEMM -> fp32 out, 128x128 tiles (grid = 128 CTAs, single wave)
    gemm_v9_kernel<128><<<dim3(LQ / 128, DIM / 128, BATCH), 256, 98304>>>(
        wph, yh, b_proj, out, qkvh, DIM, 0);
}